// round 15
// baseline (speedup 1.0000x reference)
#include <cuda_runtime.h>
#include <cuda_fp16.h>

#define NPIX  65536
#define HW4K  4096
#define CIN   256
#define KC    32          // fp32 channels per GEMM K-chunk (16 half2 rows)
#define KR2   16          // half2 rows per chunk
#define FINT  128
#define SR2   136         // smem row stride in half2 units (conflict-free)

// Scratch (device globals — no runtime allocation allowed)
__device__ float d_S[NPIX];
__device__ float d_stats[4 * FINT + 2];  // sum_g, sq_g, sum_x, sq_x, s_sum, s_sq
__device__ unsigned d_Wg2[(CIN / 2) * FINT];  // W_g packed half2 (k-pairs) [c2][o]
__device__ unsigned d_Wx2[(CIN / 2) * FINT];  // W_x packed half2 (k-pairs) [c2][o]
__device__ unsigned d_WF[(2 * CIN / 2) * FINT]; // fused scaled weights, K=512
__device__ float d_cc[FINT];             // fused per-channel constant
__device__ float d_pw[FINT];             // psi weights

// ---------------------------------------------------------------------------
// helpers
// ---------------------------------------------------------------------------
__device__ __forceinline__ unsigned packh2(float lo, float hi) {
    __half2 h = __floats2half2_rn(lo, hi);
    return *(unsigned*)&h;
}

__device__ __forceinline__ void mma16(float* c,
                                      unsigned a0, unsigned a1, unsigned a2, unsigned a3,
                                      unsigned b0, unsigned b1) {
    asm volatile(
        "mma.sync.aligned.m16n8k16.row.col.f32.f16.f16.f32 "
        "{%0,%1,%2,%3},{%4,%5,%6,%7},{%8,%9},{%0,%1,%2,%3};\n"
        : "+f"(c[0]), "+f"(c[1]), "+f"(c[2]), "+f"(c[3])
        : "r"(a0), "r"(a1), "r"(a2), "r"(a3), "r"(b0), "r"(b1));
}

__device__ __forceinline__ void cpa16(void* dst, const void* src) {
    unsigned d = (unsigned)__cvta_generic_to_shared(dst);
    asm volatile("cp.async.cg.shared.global [%0], [%1], 16;\n" :: "r"(d), "l"(src));
}
__device__ __forceinline__ void cpa_commit() {
    asm volatile("cp.async.commit_group;\n");
}

// ---------------------------------------------------------------------------
// prep: pack both weight matrices into k-pair half2 layout; zero stats.
// ---------------------------------------------------------------------------
__global__ void prep_w_kernel(const float* __restrict__ wg,
                              const float* __restrict__ wx)
{
    const int i  = blockIdx.x * 256 + threadIdx.x;   // 0..16383
    const int c2 = i >> 7;
    const int o  = i & 127;
    d_Wg2[c2 * FINT + o] = packh2(wg[o * CIN + 2 * c2], wg[o * CIN + 2 * c2 + 1]);
    d_Wx2[c2 * FINT + o] = packh2(wx[o * CIN + 2 * c2], wx[o * CIN + 2 * c2 + 1]);
    if (blockIdx.x == 0) {
        for (int k = threadIdx.x; k < 4 * FINT + 2; k += 256) d_stats[k] = 0.0f;
    }
}

// ---------------------------------------------------------------------------
// GEMM pass 1: STATS ONLY (blockIdx.y = path). No Y stores.
// y[o,p] = sum_c W[o,c]*X[b,c,hw] + bias[o]; accumulate per-channel sum/sumsq.
// Mainloop identical to the proven fp16 kernel (distance-2 X prefetch).
// ---------------------------------------------------------------------------
__global__ __launch_bounds__(256, 2)
void gemm_stats_kernel(const float* __restrict__ G,
                       const float* __restrict__ Xin,
                       const float* __restrict__ bg,
                       const float* __restrict__ bx)
{
    __shared__ __align__(16) unsigned Ws2[2][KR2][SR2];
    __shared__ __align__(16) unsigned Xs2[2][KR2][SR2];

    const int path = blockIdx.y;
    const float*    __restrict__ X    = path ? Xin : G;
    const unsigned* __restrict__ Wt   = path ? d_Wx2 : d_Wg2;
    const float*    __restrict__ bias = path ? bx : bg;
    float* __restrict__ ssum = d_stats + path * 256;
    float* __restrict__ ssq  = ssum + FINT;

    const int t    = threadIdx.x;
    const int lane = t & 31;
    const int wid  = t >> 5;
    const int g    = lane >> 2;
    const int tig  = lane & 3;
    const int m0w  = (wid >> 1) * 32;
    const int n0w  = (wid & 1) * 64;

    const int p0  = blockIdx.x * 128;
    const int b   = p0 >> 12;
    const int hw0 = p0 & 4095;
    const float* Xb = X + (size_t)b * (CIN * HW4K) + hw0;

    float acc[2][8][4];
    #pragma unroll
    for (int i = 0; i < 2; i++)
        #pragma unroll
        for (int j = 0; j < 8; j++)
            #pragma unroll
            for (int r = 0; r < 4; r++) acc[i][j][r] = 0.0f;

    int ur[2], uc[2];
    #pragma unroll
    for (int r = 0; r < 2; r++) {
        int u = t + 256 * r;
        ur[r] = u >> 5;
        uc[r] = (u & 31) * 4;
    }

    #pragma unroll
    for (int r = 0; r < 2; r++)
        cpa16(&Ws2[0][ur[r]][uc[r]], Wt + ur[r] * FINT + uc[r]);
    cpa_commit();

    float4 fl[2], fh[2];
    uint4  xpk[2];
    #pragma unroll
    for (int r = 0; r < 2; r++) {
        const float* q = Xb + (size_t)(2 * ur[r]) * HW4K + uc[r];
        fl[r] = *(const float4*)q;
        fh[r] = *(const float4*)(q + HW4K);
    }
    #pragma unroll
    for (int r = 0; r < 2; r++) {
        xpk[r].x = packh2(fl[r].x, fh[r].x);
        xpk[r].y = packh2(fl[r].y, fh[r].y);
        xpk[r].z = packh2(fl[r].z, fh[r].z);
        xpk[r].w = packh2(fl[r].w, fh[r].w);
    }
    #pragma unroll
    for (int r = 0; r < 2; r++) {
        const float* q = Xb + (size_t)(KC + 2 * ur[r]) * HW4K + uc[r];
        fl[r] = *(const float4*)q;
        fh[r] = *(const float4*)(q + HW4K);
    }

    const int NCH = CIN / KC;   // 8
    for (int ch = 0; ch < NCH; ch++) {
        const int buf = ch & 1;
        #pragma unroll
        for (int r = 0; r < 2; r++)
            *(uint4*)&Xs2[buf][ur[r]][uc[r]] = xpk[r];
        asm volatile("cp.async.wait_group 0;\n");
        __syncthreads();

        if (ch + 1 < NCH) {
            #pragma unroll
            for (int r = 0; r < 2; r++) {
                xpk[r].x = packh2(fl[r].x, fh[r].x);
                xpk[r].y = packh2(fl[r].y, fh[r].y);
                xpk[r].z = packh2(fl[r].z, fh[r].z);
                xpk[r].w = packh2(fl[r].w, fh[r].w);
            }
            const int c0 = (ch + 1) * KC;
            #pragma unroll
            for (int r = 0; r < 2; r++)
                cpa16(&Ws2[buf ^ 1][ur[r]][uc[r]],
                      Wt + (c0 / 2 + ur[r]) * FINT + uc[r]);
            cpa_commit();
            if (ch + 2 < NCH) {
                const int c2 = (ch + 2) * KC;
                #pragma unroll
                for (int r = 0; r < 2; r++) {
                    const float* q = Xb + (size_t)(c2 + 2 * ur[r]) * HW4K + uc[r];
                    fl[r] = *(const float4*)q;
                    fh[r] = *(const float4*)(q + HW4K);
                }
            }
        }

        #pragma unroll
        for (int ks = 0; ks < 2; ks++) {
            const int kb = 8 * ks;
            unsigned b0[8], b1[8];
            #pragma unroll
            for (int j = 0; j < 8; j++) {
                const int n = n0w + 8 * j + g;
                b0[j] = Xs2[buf][kb + tig][n];
                b1[j] = Xs2[buf][kb + tig + 4][n];
            }
            #pragma unroll
            for (int i = 0; i < 2; i++) {
                const int m0 = m0w + 16 * i;
                unsigned a0 = Ws2[buf][kb + tig][m0 + g];
                unsigned a1 = Ws2[buf][kb + tig][m0 + g + 8];
                unsigned a2 = Ws2[buf][kb + tig + 4][m0 + g];
                unsigned a3 = Ws2[buf][kb + tig + 4][m0 + g + 8];
                #pragma unroll
                for (int j = 0; j < 8; j++)
                    mma16(acc[i][j], a0, a1, a2, a3, b0[j], b1[j]);
            }
        }
    }

    // Epilogue: stats only
    #pragma unroll
    for (int i = 0; i < 2; i++) {
        const int r0 = m0w + 16 * i + g;
        const int r1 = r0 + 8;
        const float b0v = __ldg(&bias[r0]);
        const float b1v = __ldg(&bias[r1]);
        float s0 = 0.f, q0 = 0.f, s1 = 0.f, q1 = 0.f;
        #pragma unroll
        for (int j = 0; j < 8; j++) {
            float y00 = acc[i][j][0] + b0v, y01 = acc[i][j][1] + b0v;
            float y10 = acc[i][j][2] + b1v, y11 = acc[i][j][3] + b1v;
            s0 += y00 + y01;  q0 += y00 * y00 + y01 * y01;
            s1 += y10 + y11;  q1 += y10 * y10 + y11 * y11;
        }
        #pragma unroll
        for (int m = 1; m <= 2; m <<= 1) {
            s0 += __shfl_xor_sync(0xFFFFFFFFu, s0, m);
            q0 += __shfl_xor_sync(0xFFFFFFFFu, q0, m);
            s1 += __shfl_xor_sync(0xFFFFFFFFu, s1, m);
            q1 += __shfl_xor_sync(0xFFFFFFFFu, q1, m);
        }
        if (tig == 0) {
            atomicAdd(&ssum[r0], s0);
            atomicAdd(&ssq[r0],  q0);
            atomicAdd(&ssum[r1], s1);
            atomicAdd(&ssq[r1],  q1);
        }
    }
}

// ---------------------------------------------------------------------------
// fuse_w: compute BN coefficients from stats, bake scale into fp16 weights
// (from ORIGINAL fp32 W: single quantization), fold biases into d_cc.
// i over 32768: c2 = 0..255 (g: 0-127, x: 128-255), o = 0..127.
// ---------------------------------------------------------------------------
__global__ void fuse_w_kernel(const float* __restrict__ wg_w,
                              const float* __restrict__ wx_w,
                              const float* __restrict__ wg_b,
                              const float* __restrict__ wx_b,
                              const float* __restrict__ wg_gamma,
                              const float* __restrict__ wg_beta,
                              const float* __restrict__ wx_gamma,
                              const float* __restrict__ wx_beta,
                              const float* __restrict__ psi_w)
{
    const int i  = blockIdx.x * 256 + threadIdx.x;   // 0..32767
    const int c2 = i >> 7;
    const int o  = i & 127;
    const int path = c2 >> 7;
    const int cl2  = c2 & 127;
    const float n1 = 1.0f / (float)NPIX;

    const float* gam = path ? wx_gamma : wg_gamma;
    float mean = d_stats[path * 256 + o] * n1;
    float var  = d_stats[path * 256 + FINT + o] * n1 - mean * mean;
    float a    = gam[o] * rsqrtf(var + 1e-5f);

    const float* W = path ? wx_w : wg_w;
    d_WF[c2 * FINT + o] = packh2(a * W[o * CIN + 2 * cl2],
                                 a * W[o * CIN + 2 * cl2 + 1]);

    if (c2 == 0) {   // one thread per o computes the fused constant
        float mg = d_stats[o] * n1;
        float vg = d_stats[FINT + o] * n1 - mg * mg;
        float ag = wg_gamma[o] * rsqrtf(vg + 1e-5f);
        float mx = d_stats[2 * FINT + o] * n1;
        float vx = d_stats[3 * FINT + o] * n1 - mx * mx;
        float ax = wx_gamma[o] * rsqrtf(vx + 1e-5f);
        // z = ag*(Wg g) + ax*(Wx x) + cc;  cc folds biases and BN shifts
        d_cc[o] = ag * wg_b[o] + (wg_beta[o] - ag * mg)
                + ax * wx_b[o] + (wx_beta[o] - ax * mx);
        d_pw[o] = psi_w[o];
    }
}

// ---------------------------------------------------------------------------
// GEMM pass 2 + psi: K=512 over concatenated [g; x] with fused weights.
// Epilogue: s[p] = sum_o pw[o]*relu(z[o,p]+cc[o]) + psi_b, plus stats of s.
// ---------------------------------------------------------------------------
__global__ __launch_bounds__(256, 2)
void gemm_psi_kernel(const float* __restrict__ G,
                     const float* __restrict__ Xin,
                     const float* __restrict__ psi_b)
{
    __shared__ __align__(16) unsigned Ws2[2][KR2][SR2];
    __shared__ __align__(16) unsigned Xs2[2][KR2][SR2];
    __shared__ float sred[2][64];
    __shared__ float wsum[4], wsq[4];

    const int t    = threadIdx.x;
    const int lane = t & 31;
    const int wid  = t >> 5;
    const int g    = lane >> 2;
    const int tig  = lane & 3;
    const int m0w  = (wid >> 1) * 32;
    const int n0w  = (wid & 1) * 64;

    const int p0  = blockIdx.x * 128;
    const int b   = p0 >> 12;
    const int hw0 = p0 & 4095;
    const float* Gb = G   + (size_t)b * (CIN * HW4K) + hw0;
    const float* Xb = Xin + (size_t)b * (CIN * HW4K) + hw0;

    float acc[2][8][4];
    #pragma unroll
    for (int i = 0; i < 2; i++)
        #pragma unroll
        for (int j = 0; j < 8; j++)
            #pragma unroll
            for (int r = 0; r < 4; r++) acc[i][j][r] = 0.0f;

    int ur[2], uc[2];
    #pragma unroll
    for (int r = 0; r < 2; r++) {
        int u = t + 256 * r;
        ur[r] = u >> 5;
        uc[r] = (u & 31) * 4;
    }

    // chunk -> source row pointer (chunks 0-7: g, 8-15: x)
    #define XROW(ch, row) ((ch) < 8 ? Gb + (size_t)((ch) * KC + (row)) * HW4K \
                                    : Xb + (size_t)(((ch) - 8) * KC + (row)) * HW4K)

    #pragma unroll
    for (int r = 0; r < 2; r++)
        cpa16(&Ws2[0][ur[r]][uc[r]], d_WF + ur[r] * FINT + uc[r]);
    cpa_commit();

    float4 fl[2], fh[2];
    uint4  xpk[2];
    #pragma unroll
    for (int r = 0; r < 2; r++) {
        const float* q = XROW(0, 2 * ur[r]) + uc[r];
        fl[r] = *(const float4*)q;
        fh[r] = *(const float4*)(q + HW4K);
    }
    #pragma unroll
    for (int r = 0; r < 2; r++) {
        xpk[r].x = packh2(fl[r].x, fh[r].x);
        xpk[r].y = packh2(fl[r].y, fh[r].y);
        xpk[r].z = packh2(fl[r].z, fh[r].z);
        xpk[r].w = packh2(fl[r].w, fh[r].w);
    }
    #pragma unroll
    for (int r = 0; r < 2; r++) {
        const float* q = XROW(1, 2 * ur[r]) + uc[r];
        fl[r] = *(const float4*)q;
        fh[r] = *(const float4*)(q + HW4K);
    }

    const int NCH = 16;   // K = 512
    for (int ch = 0; ch < NCH; ch++) {
        const int buf = ch & 1;
        #pragma unroll
        for (int r = 0; r < 2; r++)
            *(uint4*)&Xs2[buf][ur[r]][uc[r]] = xpk[r];
        asm volatile("cp.async.wait_group 0;\n");
        __syncthreads();

        if (ch + 1 < NCH) {
            #pragma unroll
            for (int r = 0; r < 2; r++) {
                xpk[r].x = packh2(fl[r].x, fh[r].x);
                xpk[r].y = packh2(fl[r].y, fh[r].y);
                xpk[r].z = packh2(fl[r].z, fh[r].z);
                xpk[r].w = packh2(fl[r].w, fh[r].w);
            }
            #pragma unroll
            for (int r = 0; r < 2; r++)
                cpa16(&Ws2[buf ^ 1][ur[r]][uc[r]],
                      d_WF + ((ch + 1) * KR2 + ur[r]) * FINT + uc[r]);
            cpa_commit();
            if (ch + 2 < NCH) {
                #pragma unroll
                for (int r = 0; r < 2; r++) {
                    const float* q = XROW(ch + 2, 2 * ur[r]) + uc[r];
                    fl[r] = *(const float4*)q;
                    fh[r] = *(const float4*)(q + HW4K);
                }
            }
        }

        #pragma unroll
        for (int ks = 0; ks < 2; ks++) {
            const int kb = 8 * ks;
            unsigned b0[8], b1[8];
            #pragma unroll
            for (int j = 0; j < 8; j++) {
                const int n = n0w + 8 * j + g;
                b0[j] = Xs2[buf][kb + tig][n];
                b1[j] = Xs2[buf][kb + tig + 4][n];
            }
            #pragma unroll
            for (int i = 0; i < 2; i++) {
                const int m0 = m0w + 16 * i;
                unsigned a0 = Ws2[buf][kb + tig][m0 + g];
                unsigned a1 = Ws2[buf][kb + tig][m0 + g + 8];
                unsigned a2 = Ws2[buf][kb + tig + 4][m0 + g];
                unsigned a3 = Ws2[buf][kb + tig + 4][m0 + g + 8];
                #pragma unroll
                for (int j = 0; j < 8; j++)
                    mma16(acc[i][j], a0, a1, a2, a3, b0[j], b1[j]);
            }
        }
    }
    #undef XROW

    // Epilogue: relu + psi_w weighted channel-sum -> s[p] for 128 px
    if (t < 128) { sred[t >> 6][t & 63] = 0.0f; }
    __syncthreads();

    float spx[8][2];
    #pragma unroll
    for (int j = 0; j < 8; j++) { spx[j][0] = 0.f; spx[j][1] = 0.f; }
    #pragma unroll
    for (int i = 0; i < 2; i++) {
        const int r0 = m0w + 16 * i + g;
        const int r1 = r0 + 8;
        const float cc0 = __ldg(&d_cc[r0]), cc1 = __ldg(&d_cc[r1]);
        const float pw0 = __ldg(&d_pw[r0]), pw1 = __ldg(&d_pw[r1]);
        #pragma unroll
        for (int j = 0; j < 8; j++) {
            spx[j][0] += pw0 * fmaxf(acc[i][j][0] + cc0, 0.f)
                       + pw1 * fmaxf(acc[i][j][2] + cc1, 0.f);
            spx[j][1] += pw0 * fmaxf(acc[i][j][1] + cc0, 0.f)
                       + pw1 * fmaxf(acc[i][j][3] + cc1, 0.f);
        }
    }
    // reduce over g (lane bits [2:4])
    #pragma unroll
    for (int j = 0; j < 8; j++)
        #pragma unroll
        for (int u = 0; u < 2; u++) {
            spx[j][u] += __shfl_xor_sync(0xFFFFFFFFu, spx[j][u], 4);
            spx[j][u] += __shfl_xor_sync(0xFFFFFFFFu, spx[j][u], 8);
            spx[j][u] += __shfl_xor_sync(0xFFFFFFFFu, spx[j][u], 16);
        }
    if (g == 0) {   // lanes 0..3 (tig) of every warp
        const int ng = wid & 1;
        #pragma unroll
        for (int j = 0; j < 8; j++) {
            atomicAdd(&sred[ng][8 * j + 2 * tig + 0], spx[j][0]);
            atomicAdd(&sred[ng][8 * j + 2 * tig + 1], spx[j][1]);
        }
    }
    __syncthreads();

    if (t < 128) {
        float s = sred[t >> 6][t & 63] + __ldg(psi_b);
        d_S[p0 + t] = s;
        float q = s * s;
        #pragma unroll
        for (int m = 16; m >= 1; m >>= 1) {
            s += __shfl_xor_sync(0xFFFFFFFFu, s, m);
            q += __shfl_xor_sync(0xFFFFFFFFu, q, m);
        }
        if (lane == 0) { wsum[wid] = s; wsq[wid] = q; }
    }
    __syncthreads();
    if (t == 0) {
        atomicAdd(&d_stats[4 * FINT + 0], wsum[0] + wsum[1] + wsum[2] + wsum[3]);
        atomicAdd(&d_stats[4 * FINT + 1], wsq[0] + wsq[1] + wsq[2] + wsq[3]);
    }
}

// ---------------------------------------------------------------------------
// out: inlines final BN affine:
// out[b,c,hw] = x[b,c,hw] * sigmoid(a*s[p] + c)
// ---------------------------------------------------------------------------
__global__ __launch_bounds__(256)
void out_kernel(const float* __restrict__ X, float* __restrict__ O,
                const float* __restrict__ psi_gamma,
                const float* __restrict__ psi_beta)
{
    const float n1 = 1.0f / (float)NPIX;
    const float m = d_stats[4 * FINT + 0] * n1;
    const float v = d_stats[4 * FINT + 1] * n1 - m * m;
    const float a = psi_gamma[0] * rsqrtf(v + 1e-5f);
    const float c = psi_beta[0] - a * m;

    const size_t i = (size_t)blockIdx.x * 256 + threadIdx.x;
    const size_t e = i * 4;
    const int bidx = (int)(e >> 20);
    const int hw   = (int)(e & 4095);
    const int p    = (bidx << 12) + hw;

    float4 xv = *(const float4*)(X + e);
    float4 sv = *(const float4*)(d_S + p);
    float4 r;
    r.x = __fdividef(xv.x, 1.0f + __expf(-fmaf(a, sv.x, c)));
    r.y = __fdividef(xv.y, 1.0f + __expf(-fmaf(a, sv.y, c)));
    r.z = __fdividef(xv.z, 1.0f + __expf(-fmaf(a, sv.z, c)));
    r.w = __fdividef(xv.w, 1.0f + __expf(-fmaf(a, sv.w, c)));
    *(float4*)(O + e) = r;
}

// ---------------------------------------------------------------------------
extern "C" void kernel_launch(void* const* d_in, const int* in_sizes, int n_in,
                              void* d_out, int out_size)
{
    const float* g         = (const float*)d_in[0];
    const float* x         = (const float*)d_in[1];
    const float* wg_w      = (const float*)d_in[2];
    const float* wg_b      = (const float*)d_in[3];
    const float* wg_gamma  = (const float*)d_in[4];
    const float* wg_beta   = (const float*)d_in[5];
    const float* wx_w      = (const float*)d_in[6];
    const float* wx_b      = (const float*)d_in[7];
    const float* wx_gamma  = (const float*)d_in[8];
    const float* wx_beta   = (const float*)d_in[9];
    const float* psi_w     = (const float*)d_in[10];
    const float* psi_b     = (const float*)d_in[11];
    const float* psi_gamma = (const float*)d_in[12];
    const float* psi_beta  = (const float*)d_in[13];
    float* out = (float*)d_out;

    prep_w_kernel<<<(CIN / 2 * FINT) / 256, 256>>>(wg_w, wx_w);
    gemm_stats_kernel<<<dim3(NPIX / 128, 2), 256>>>(g, x, wg_b, wx_b);
    fuse_w_kernel<<<(2 * CIN / 2 * FINT) / 256, 256>>>(wg_w, wx_w, wg_b, wx_b,
                                                       wg_gamma, wg_beta,
                                                       wx_gamma, wx_beta, psi_w);
    gemm_psi_kernel<<<NPIX / 128, 256>>>(g, x, psi_b);
    out_kernel<<<(16 * CIN * HW4K) / (4 * 256), 256>>>(x, out, psi_gamma, psi_beta);
}

// round 16
// speedup vs baseline: 1.3659x; 1.3659x over previous
#include <cuda_runtime.h>
#include <cuda_fp16.h>

#define NPIX  65536
#define HW4K  4096
#define CIN   256
#define KC    32          // fp32 channels per GEMM K-chunk (16 half2 rows)
#define KR2   16          // half2 rows per chunk
#define FINT  128
#define SR2   136         // smem row stride in half2 units (conflict-free)

// Scratch (device globals — no runtime allocation allowed)
__device__ unsigned d_Ygh[FINT * NPIX / 2];   // Y_g as fp16x2 pairs (16.8 MB)
__device__ unsigned d_Yxh[FINT * NPIX / 2];   // Y_x as fp16x2 pairs
__device__ float d_S[NPIX];
__device__ float d_stats[4 * FINT + 2];  // sum_g, sq_g, sum_x, sq_x, s_sum, s_sq
__device__ unsigned d_Wg2[(CIN / 2) * FINT];  // W_g packed half2 (k-pairs) [c2][o]
__device__ unsigned d_Wx2[(CIN / 2) * FINT];  // W_x packed half2 (k-pairs) [c2][o]

// ---------------------------------------------------------------------------
// helpers
// ---------------------------------------------------------------------------
__device__ __forceinline__ unsigned packh2(float lo, float hi) {
    __half2 h = __floats2half2_rn(lo, hi);
    return *(unsigned*)&h;
}

__device__ __forceinline__ void mma16(float* c,
                                      unsigned a0, unsigned a1, unsigned a2, unsigned a3,
                                      unsigned b0, unsigned b1) {
    asm volatile(
        "mma.sync.aligned.m16n8k16.row.col.f32.f16.f16.f32 "
        "{%0,%1,%2,%3},{%4,%5,%6,%7},{%8,%9},{%0,%1,%2,%3};\n"
        : "+f"(c[0]), "+f"(c[1]), "+f"(c[2]), "+f"(c[3])
        : "r"(a0), "r"(a1), "r"(a2), "r"(a3), "r"(b0), "r"(b1));
}

__device__ __forceinline__ void cpa16(void* dst, const void* src) {
    unsigned d = (unsigned)__cvta_generic_to_shared(dst);
    asm volatile("cp.async.cg.shared.global [%0], [%1], 16;\n" :: "r"(d), "l"(src));
}
__device__ __forceinline__ void cpa_commit() {
    asm volatile("cp.async.commit_group;\n");
}

// ---------------------------------------------------------------------------
// prep: pack both weight matrices into k-pair half2 layout:
//   d_W2[c2 * FINT + o] = half2(W[o][2*c2], W[o][2*c2+1])
// block 0 also zeroes the stats accumulators.
// ---------------------------------------------------------------------------
__global__ void prep_w_kernel(const float* __restrict__ wg,
                              const float* __restrict__ wx)
{
    const int i  = blockIdx.x * 256 + threadIdx.x;   // 0..16383
    const int c2 = i >> 7;
    const int o  = i & 127;
    d_Wg2[c2 * FINT + o] = packh2(wg[o * CIN + 2 * c2], wg[o * CIN + 2 * c2 + 1]);
    d_Wx2[c2 * FINT + o] = packh2(wx[o * CIN + 2 * c2], wx[o * CIN + 2 * c2 + 1]);
    if (blockIdx.x == 0) {
        for (int k = threadIdx.x; k < 4 * FINT + 2; k += 256) d_stats[k] = 0.0f;
    }
}

// ---------------------------------------------------------------------------
// Fused fp16 tensor-core GEMMs (blockIdx.y = path: 0 -> g, 1 -> x).
// Y[o,p] = sum_c W[o,c]*X[b,c,hw] + bias[o]   (fp16 mma.m16n8k16, fp32 accum)
// CTA: 128 channels x 128 pixels, 8 warps, warp tile 32(ch) x 64(px).
// KC=32 chunks, ONE barrier per chunk. X prefetch at DISTANCE 2.
// Epilogue: bias add, fp16x2 store of Y, per-channel fp32 sum/sumsq atomics.
// ---------------------------------------------------------------------------
__global__ __launch_bounds__(256, 2)
void gemm_tc_kernel(const float* __restrict__ G,
                    const float* __restrict__ Xin,
                    const float* __restrict__ bg,
                    const float* __restrict__ bx)
{
    __shared__ __align__(16) unsigned Ws2[2][KR2][SR2];
    __shared__ __align__(16) unsigned Xs2[2][KR2][SR2];

    const int path = blockIdx.y;
    const float*    __restrict__ X    = path ? Xin : G;
    const unsigned* __restrict__ Wt   = path ? d_Wx2 : d_Wg2;
    const float*    __restrict__ bias = path ? bx : bg;
    unsigned* __restrict__ Yh   = path ? d_Yxh : d_Ygh;
    float* __restrict__ ssum = d_stats + path * 256;
    float* __restrict__ ssq  = ssum + FINT;

    const int t    = threadIdx.x;
    const int lane = t & 31;
    const int wid  = t >> 5;            // 0..7
    const int g    = lane >> 2;         // 0..7
    const int tig  = lane & 3;          // 0..3
    const int m0w  = (wid >> 1) * 32;   // 4 m-warps
    const int n0w  = (wid & 1) * 64;    // 2 n-warps

    const int p0  = blockIdx.x * 128;
    const int b   = p0 >> 12;
    const int hw0 = p0 & 4095;
    const float* Xb = X + (size_t)b * (CIN * HW4K) + hw0;

    float acc[2][8][4];
    #pragma unroll
    for (int i = 0; i < 2; i++)
        #pragma unroll
        for (int j = 0; j < 8; j++)
            #pragma unroll
            for (int r = 0; r < 4; r++) acc[i][j][r] = 0.0f;

    int ur[2], uc[2];
    #pragma unroll
    for (int r = 0; r < 2; r++) {
        int u = t + 256 * r;
        ur[r] = u >> 5;              // half2 row 0..15
        uc[r] = (u & 31) * 4;        // col
    }

    // prologue: W chunk0 via cp.async; X chunk0 -> pack; X chunk1 LDG in flight
    #pragma unroll
    for (int r = 0; r < 2; r++)
        cpa16(&Ws2[0][ur[r]][uc[r]], Wt + ur[r] * FINT + uc[r]);
    cpa_commit();

    float4 fl[2], fh[2];
    uint4  xpk[2];
    #pragma unroll
    for (int r = 0; r < 2; r++) {
        const float* q = Xb + (size_t)(2 * ur[r]) * HW4K + uc[r];
        fl[r] = *(const float4*)q;
        fh[r] = *(const float4*)(q + HW4K);
    }
    #pragma unroll
    for (int r = 0; r < 2; r++) {
        xpk[r].x = packh2(fl[r].x, fh[r].x);
        xpk[r].y = packh2(fl[r].y, fh[r].y);
        xpk[r].z = packh2(fl[r].z, fh[r].z);
        xpk[r].w = packh2(fl[r].w, fh[r].w);
    }
    #pragma unroll
    for (int r = 0; r < 2; r++) {
        const float* q = Xb + (size_t)(KC + 2 * ur[r]) * HW4K + uc[r];
        fl[r] = *(const float4*)q;
        fh[r] = *(const float4*)(q + HW4K);
    }

    const int NCH = CIN / KC;   // 8 chunks
    for (int ch = 0; ch < NCH; ch++) {
        const int buf = ch & 1;
        #pragma unroll
        for (int r = 0; r < 2; r++)
            *(uint4*)&Xs2[buf][ur[r]][uc[r]] = xpk[r];
        asm volatile("cp.async.wait_group 0;\n");   // W(buf) arrived
        __syncthreads();

        if (ch + 1 < NCH) {
            #pragma unroll
            for (int r = 0; r < 2; r++) {
                xpk[r].x = packh2(fl[r].x, fh[r].x);
                xpk[r].y = packh2(fl[r].y, fh[r].y);
                xpk[r].z = packh2(fl[r].z, fh[r].z);
                xpk[r].w = packh2(fl[r].w, fh[r].w);
            }
            const int c0 = (ch + 1) * KC;
            #pragma unroll
            for (int r = 0; r < 2; r++)
                cpa16(&Ws2[buf ^ 1][ur[r]][uc[r]],
                      Wt + (c0 / 2 + ur[r]) * FINT + uc[r]);
            cpa_commit();
            if (ch + 2 < NCH) {
                const int c2 = (ch + 2) * KC;
                #pragma unroll
                for (int r = 0; r < 2; r++) {
                    const float* q = Xb + (size_t)(c2 + 2 * ur[r]) * HW4K + uc[r];
                    fl[r] = *(const float4*)q;
                    fh[r] = *(const float4*)(q + HW4K);
                }
            }
        }

        #pragma unroll
        for (int ks = 0; ks < 2; ks++) {
            const int kb = 8 * ks;
            unsigned b0[8], b1[8];
            #pragma unroll
            for (int j = 0; j < 8; j++) {
                const int n = n0w + 8 * j + g;
                b0[j] = Xs2[buf][kb + tig][n];
                b1[j] = Xs2[buf][kb + tig + 4][n];
            }
            #pragma unroll
            for (int i = 0; i < 2; i++) {
                const int m0 = m0w + 16 * i;
                unsigned a0 = Ws2[buf][kb + tig][m0 + g];
                unsigned a1 = Ws2[buf][kb + tig][m0 + g + 8];
                unsigned a2 = Ws2[buf][kb + tig + 4][m0 + g];
                unsigned a3 = Ws2[buf][kb + tig + 4][m0 + g + 8];
                #pragma unroll
                for (int j = 0; j < 8; j++)
                    mma16(acc[i][j], a0, a1, a2, a3, b0[j], b1[j]);
            }
        }
    }

    // Epilogue: bias, fp16x2 store of Y, per-channel fp32 stats
    #pragma unroll
    for (int i = 0; i < 2; i++) {
        const int r0 = m0w + 16 * i + g;
        const int r1 = r0 + 8;
        const float b0v = __ldg(&bias[r0]);
        const float b1v = __ldg(&bias[r1]);
        float s0 = 0.f, q0 = 0.f, s1 = 0.f, q1 = 0.f;
        #pragma unroll
        for (int j = 0; j < 8; j++) {
            float y00 = acc[i][j][0] + b0v, y01 = acc[i][j][1] + b0v;
            float y10 = acc[i][j][2] + b1v, y11 = acc[i][j][3] + b1v;
            const int col = p0 + n0w + 8 * j + 2 * tig;   // even
            Yh[((size_t)r0 * NPIX + col) >> 1] = packh2(y00, y01);
            Yh[((size_t)r1 * NPIX + col) >> 1] = packh2(y10, y11);
            s0 += y00 + y01;  q0 += y00 * y00 + y01 * y01;
            s1 += y10 + y11;  q1 += y10 * y10 + y11 * y11;
        }
        #pragma unroll
        for (int m = 1; m <= 2; m <<= 1) {
            s0 += __shfl_xor_sync(0xFFFFFFFFu, s0, m);
            q0 += __shfl_xor_sync(0xFFFFFFFFu, q0, m);
            s1 += __shfl_xor_sync(0xFFFFFFFFu, s1, m);
            q1 += __shfl_xor_sync(0xFFFFFFFFu, q1, m);
        }
        if (tig == 0) {
            atomicAdd(&ssum[r0], s0);
            atomicAdd(&ssq[r0],  q0);
            atomicAdd(&ssum[r1], s1);
            atomicAdd(&ssq[r1],  q1);
        }
    }
}

// ---------------------------------------------------------------------------
// psi: inlines BN-coefficient computation, then
// s[p] = sum_o psi_w[o]*relu(ag*yg + ax*yx + cc) + psi_b, plus stats of s.
// 64 threads x 2 px -> 128 px/CTA, grid = 512 (3.46 waves: full-chip balance).
// unroll 16 (32 outstanding 4B loads per thread).
// ---------------------------------------------------------------------------
__global__ __launch_bounds__(64)
void psi_kernel(const float* __restrict__ wg_gamma,
                const float* __restrict__ wg_beta,
                const float* __restrict__ wx_gamma,
                const float* __restrict__ wx_beta,
                const float* __restrict__ psi_w,
                const float* __restrict__ psi_b)
{
    __shared__ float ags[FINT], axs[FINT], ccs[FINT], pws[FINT];
    const int t = threadIdx.x;   // 0..63
    #pragma unroll
    for (int o = t; o < FINT; o += 64) {
        const float n1 = 1.0f / (float)NPIX;
        float mg = d_stats[o] * n1;
        float vg = d_stats[FINT + o] * n1 - mg * mg;
        float ag = wg_gamma[o] * rsqrtf(vg + 1e-5f);
        float cg = wg_beta[o] - ag * mg;
        float mx = d_stats[2 * FINT + o] * n1;
        float vx = d_stats[3 * FINT + o] * n1 - mx * mx;
        float ax = wx_gamma[o] * rsqrtf(vx + 1e-5f);
        float cx = wx_beta[o] - ax * mx;
        ags[o] = ag;
        axs[o] = ax;
        ccs[o] = cg + cx;
        pws[o] = psi_w[o];
    }
    __syncthreads();

    const int p = (blockIdx.x * 64 + t) * 2;        // grid = NPIX/128
    const size_t ph = (size_t)p >> 1;
    float ax0 = 0.f, ax1 = 0.f;
    #pragma unroll 16
    for (int o = 0; o < FINT; o++) {
        const size_t idx = ((size_t)o * NPIX >> 1) + ph;
        float2 vg = __half22float2(*(const __half2*)&d_Ygh[idx]);
        float2 vx = __half22float2(*(const __half2*)&d_Yxh[idx]);
        const float ag = ags[o], axx = axs[o], cc = ccs[o], pw = pws[o];
        ax0 = fmaf(pw, fmaxf(fmaf(ag, vg.x, fmaf(axx, vx.x, cc)), 0.f), ax0);
        ax1 = fmaf(pw, fmaxf(fmaf(ag, vg.y, fmaf(axx, vx.y, cc)), 0.f), ax1);
    }
    const float pb = psi_b[0];
    ax0 += pb; ax1 += pb;
    *(float2*)&d_S[p] = make_float2(ax0, ax1);

    float s = ax0 + ax1;
    float q = ax0 * ax0 + ax1 * ax1;
    #pragma unroll
    for (int m = 16; m >= 1; m >>= 1) {
        s += __shfl_xor_sync(0xFFFFFFFFu, s, m);
        q += __shfl_xor_sync(0xFFFFFFFFu, q, m);
    }
    __shared__ float ws[2], wq[2];
    const int lane = t & 31, w = t >> 5;
    if (lane == 0) { ws[w] = s; wq[w] = q; }
    __syncthreads();
    if (t == 0) {
        atomicAdd(&d_stats[4 * FINT + 0], ws[0] + ws[1]);
        atomicAdd(&d_stats[4 * FINT + 1], wq[0] + wq[1]);
    }
}

// ---------------------------------------------------------------------------
// out: inlines final BN affine:
// out[b,c,hw] = x[b,c,hw] * sigmoid(a*s[p] + c)    (fast exp/div, 4 elems/thread)
// ---------------------------------------------------------------------------
__global__ __launch_bounds__(256)
void out_kernel(const float* __restrict__ X, float* __restrict__ O,
                const float* __restrict__ psi_gamma,
                const float* __restrict__ psi_beta)
{
    const float n1 = 1.0f / (float)NPIX;
    const float m = d_stats[4 * FINT + 0] * n1;
    const float v = d_stats[4 * FINT + 1] * n1 - m * m;
    const float a = psi_gamma[0] * rsqrtf(v + 1e-5f);
    const float c = psi_beta[0] - a * m;

    const size_t i = (size_t)blockIdx.x * 256 + threadIdx.x;
    const size_t e = i * 4;
    const int bidx = (int)(e >> 20);       // / (256*4096)
    const int hw   = (int)(e & 4095);
    const int p    = (bidx << 12) + hw;

    float4 xv = *(const float4*)(X + e);
    float4 sv = *(const float4*)(d_S + p);
    float4 r;
    r.x = __fdividef(xv.x, 1.0f + __expf(-fmaf(a, sv.x, c)));
    r.y = __fdividef(xv.y, 1.0f + __expf(-fmaf(a, sv.y, c)));
    r.z = __fdividef(xv.z, 1.0f + __expf(-fmaf(a, sv.z, c)));
    r.w = __fdividef(xv.w, 1.0f + __expf(-fmaf(a, sv.w, c)));
    *(float4*)(O + e) = r;
}

// ---------------------------------------------------------------------------
extern "C" void kernel_launch(void* const* d_in, const int* in_sizes, int n_in,
                              void* d_out, int out_size)
{
    const float* g         = (const float*)d_in[0];
    const float* x         = (const float*)d_in[1];
    const float* wg_w      = (const float*)d_in[2];
    const float* wg_b      = (const float*)d_in[3];
    const float* wg_gamma  = (const float*)d_in[4];
    const float* wg_beta   = (const float*)d_in[5];
    const float* wx_w      = (const float*)d_in[6];
    const float* wx_b      = (const float*)d_in[7];
    const float* wx_gamma  = (const float*)d_in[8];
    const float* wx_beta   = (const float*)d_in[9];
    const float* psi_w     = (const float*)d_in[10];
    const float* psi_b     = (const float*)d_in[11];
    const float* psi_gamma = (const float*)d_in[12];
    const float* psi_beta  = (const float*)d_in[13];
    float* out = (float*)d_out;

    prep_w_kernel<<<(CIN / 2 * FINT) / 256, 256>>>(wg_w, wx_w);
    gemm_tc_kernel<<<dim3(NPIX / 128, 2), 256>>>(g, x, wg_b, wx_b);
    psi_kernel<<<NPIX / 128, 64>>>(wg_gamma, wg_beta, wx_gamma, wx_beta,
                                   psi_w, psi_b);
    out_kernel<<<(16 * CIN * HW4K) / (4 * 256), 256>>>(x, out, psi_gamma, psi_beta);
}